// round 9
// baseline (speedup 1.0000x reference)
#include <cuda_runtime.h>

#define NN     16384
#define FEAT   512
#define H1D    256
#define H2D    64
#define CAP    128
#define SCAN_BLOCKS 148
#define K1_GRID (SCAN_BLOCKS + 148)   // one scan CTA + one GEMM CTA per SM
#define K4_BLOCKS 1024                // 16 rows per block (2 per warp)

#define STAGE_F4 64                   // float4 per scan stage (1 KB)
#define DEPTH    4                    // smem ring depth per warp
#define STAGES   (NN / 4 / STAGE_F4)  // 64 stages per row

// ---------------- scratch (static device arrays: allowed) ----------------
__device__ unsigned short g_cols[(size_t)NN * CAP];   // 4 MB
__device__ float          g_vals[(size_t)NN * CAP];   // 8 MB
__device__ int            g_cnt [NN];
__device__ float          g_P1  [(size_t)NN * H1D];   // 16 MB  x@W1
__device__ float          g_H1  [(size_t)NN * H1D];   // 16 MB  relu(A p1 + b1)
__device__ float          g_P2  [(size_t)NN * H2D];   // 4 MB   H1@W2
__device__ float          g_pmax[K4_BLOCKS * H2D];    // per-block column maxima

typedef unsigned long long ull;

__device__ __forceinline__ ull dup2(float a) {
    ull r; asm("mov.b64 %0, {%1,%1};" : "=l"(r) : "f"(a)); return r;
}
__device__ __forceinline__ void ffma2(ull& d, ull a, ull b) {
    asm("fma.rn.f32x2 %0, %1, %2, %0;" : "+l"(d) : "l"(a), "l"(b));
}
__device__ __forceinline__ float2 unpack2(ull v) {
    float2 r; asm("mov.b64 {%0,%1}, %2;" : "=f"(r.x), "=f"(r.y) : "l"(v)); return r;
}
__device__ __forceinline__ void cp16(void* smem_dst, const void* gmem_src) {
    unsigned saddr = (unsigned)__cvta_generic_to_shared(smem_dst);
    asm volatile("cp.async.cg.shared.global [%0], [%1], 16;\n"
                 :: "r"(saddr), "l"(gmem_src) : "memory");
}
__device__ __forceinline__ void cp_commit() {
    asm volatile("cp.async.commit_group;\n" ::: "memory");
}
__device__ __forceinline__ void cp_wait3() {
    asm volatile("cp.async.wait_group 3;\n" ::: "memory");
}

// ============================================================================
// K1: fused  (a) adj sparsify scan — blocks [0,148): warp-per-row,
//                cp.async 4-deep smem ring (zero register pressure, ~24KB/SM
//                in flight) + deterministic ballot compaction
//            (b) P1 = x@W1 fp32 GEMM — blocks [148,296): grid-stride over
//                256 tiles of 128x128, FFMA2 inner loop
//     Both branches overlay a 32 KB static smem pool.
// ============================================================================
__global__ void __launch_bounds__(256, 2)
k1_scan_gemm(const float* __restrict__ x,
             const float* __restrict__ adj,
             const float* __restrict__ W1) {
    __shared__ __align__(16) char s_pool[32768];

    if (blockIdx.x < SCAN_BLOCKS) {
        int lane = threadIdx.x & 31;
        int w    = threadIdx.x >> 5;
        unsigned lt = (1u << lane) - 1u;
        float4* wbuf = ((float4*)s_pool) + w * (DEPTH * STAGE_F4);   // 4 KB/warp

        for (int row = blockIdx.x * 8 + w; row < NN; row += SCAN_BLOCKS * 8) {
            const float4* r4 = (const float4*)(adj + (size_t)row * NN);
            int base = row * CAP;
            int cnt  = 0;

            // prologue: issue stages 0..2
            #pragma unroll
            for (int p = 0; p < DEPTH - 1; ++p) {
                const float4* src = r4 + p * STAGE_F4;
                #pragma unroll
                for (int u = 0; u < STAGE_F4 / 32; ++u)
                    cp16(&wbuf[p * STAGE_F4 + u * 32 + lane], &src[u * 32 + lane]);
                cp_commit();
            }

            for (int s = 0; s < STAGES; ++s) {
                int nx = s + (DEPTH - 1);
                if (nx < STAGES) {                       // issue stage s+3
                    int slot = nx & (DEPTH - 1);
                    const float4* src = r4 + nx * STAGE_F4;
                    #pragma unroll
                    for (int u = 0; u < STAGE_F4 / 32; ++u)
                        cp16(&wbuf[slot * STAGE_F4 + u * 32 + lane], &src[u * 32 + lane]);
                }
                cp_commit();                             // empty group at tail keeps count uniform
                cp_wait3();                              // stage s now resident

                int slot = s & (DEPTH - 1);
                #pragma unroll
                for (int u = 0; u < STAGE_F4 / 32; ++u) {
                    float4 vv = wbuf[slot * STAGE_F4 + u * 32 + lane];
                    int colbase = 4 * (s * STAGE_F4 + u * 32 + lane);
                    bool any = (vv.x != 0.f) || (vv.y != 0.f) || (vv.z != 0.f) || (vv.w != 0.f);
                    unsigned m4 = __ballot_sync(0xffffffffu, any);
                    if (m4 == 0u) continue;              // most chunks all-zero
                    float arr[4] = {vv.x, vv.y, vv.z, vv.w};
                    #pragma unroll
                    for (int c2 = 0; c2 < 4; ++c2) {
                        float val = arr[c2];
                        unsigned m = __ballot_sync(0xffffffffu, val != 0.f);
                        if (val != 0.f) {
                            int off = cnt + __popc(m & lt);
                            if (off < CAP) {
                                g_cols[base + off] = (unsigned short)(colbase + c2);
                                g_vals[base + off] = val;
                            }
                        }
                        cnt += __popc(m);
                    }
                }
            }
            if (lane == 0) g_cnt[row] = cnt < CAP ? cnt : CAP;
        }
    } else {
        // ---- GEMM: P1[16384,256] = x[16384,512] @ W1[512,256] ----
        float* As = (float*)s_pool;              // [k][m]  8 KB
        float* Bs = (float*)(s_pool + 8192);     // [k][n]  8 KB
        int tid = threadIdx.x;
        int tx = tid & 15, ty = tid >> 4;

        for (int t = blockIdx.x - SCAN_BLOCKS; t < 256; t += 148) {
            int row_base = (t >> 1) * 128;
            int col_base = (t & 1) * 128;

            ull acc[8][4];
            #pragma unroll
            for (int r = 0; r < 8; ++r)
                #pragma unroll
                for (int c = 0; c < 4; ++c) acc[r][c] = 0ull;

            for (int kb = 0; kb < FEAT; kb += 16) {
                #pragma unroll
                for (int l = 0; l < 2; ++l) {              // A: 512 float4
                    int idx = tid + l * 256;
                    int m  = idx & 127;
                    int kq = idx >> 7;                      // 0..3
                    float4 v = __ldg((const float4*)&x[(size_t)(row_base + m) * FEAT + kb + kq * 4]);
                    As[(kq * 4 + 0) * 128 + m] = v.x;
                    As[(kq * 4 + 1) * 128 + m] = v.y;
                    As[(kq * 4 + 2) * 128 + m] = v.z;
                    As[(kq * 4 + 3) * 128 + m] = v.w;
                }
                #pragma unroll
                for (int l = 0; l < 2; ++l) {              // B: 512 float4
                    int idx = tid + l * 256;
                    int kk = idx >> 5;                      // 0..15
                    int nq = idx & 31;
                    float4 v = __ldg((const float4*)&W1[(size_t)(kb + kk) * H1D + col_base + nq * 4]);
                    *(float4*)&Bs[kk * 128 + nq * 4] = v;
                }
                __syncthreads();
                #pragma unroll
                for (int kk = 0; kk < 16; ++kk) {
                    float4 a0 = *(float4*)&As[kk * 128 + ty * 8];
                    float4 a1 = *(float4*)&As[kk * 128 + ty * 8 + 4];
                    ull b0 = *(ull*)&Bs[kk * 128 + tx * 8];
                    ull b1 = *(ull*)&Bs[kk * 128 + tx * 8 + 2];
                    ull b2 = *(ull*)&Bs[kk * 128 + tx * 8 + 4];
                    ull b3 = *(ull*)&Bs[kk * 128 + tx * 8 + 6];
                    float av[8] = {a0.x, a0.y, a0.z, a0.w, a1.x, a1.y, a1.z, a1.w};
                    #pragma unroll
                    for (int r = 0; r < 8; ++r) {
                        ull ad = dup2(av[r]);
                        ffma2(acc[r][0], ad, b0);
                        ffma2(acc[r][1], ad, b1);
                        ffma2(acc[r][2], ad, b2);
                        ffma2(acc[r][3], ad, b3);
                    }
                }
                __syncthreads();
            }
            #pragma unroll
            for (int r = 0; r < 8; ++r) {
                int row = row_base + ty * 8 + r;
                float2 p0 = unpack2(acc[r][0]);
                float2 p1 = unpack2(acc[r][1]);
                float2 p2 = unpack2(acc[r][2]);
                float2 p3 = unpack2(acc[r][3]);
                *(float4*)&g_P1[(size_t)row * H1D + col_base + tx * 8]     = make_float4(p0.x, p0.y, p1.x, p1.y);
                *(float4*)&g_P1[(size_t)row * H1D + col_base + tx * 8 + 4] = make_float4(p2.x, p2.y, p3.x, p3.y);
            }
        }
    }
}

// ============================================================================
// K2: H1[row, c] = relu(b1[c] + sum_k val_k * P1[col_k, c])   (block per row)
// ============================================================================
__global__ void __launch_bounds__(256)
k2_spmm1(const float* __restrict__ b1) {
    int row = blockIdx.x;
    int tid = threadIdx.x;
    __shared__ int   sc[CAP];
    __shared__ float sv[CAP];
    int cnt = g_cnt[row];
    if (tid < cnt) {
        sc[tid] = g_cols[row * CAP + tid];
        sv[tid] = g_vals[row * CAP + tid];
    }
    __syncthreads();
    float acc = __ldg(&b1[tid]);
    int k = 0;
    for (; k + 8 <= cnt; k += 8) {                 // 8 gathers in flight
        float p[8];
        #pragma unroll
        for (int u = 0; u < 8; ++u)
            p[u] = g_P1[(size_t)sc[k + u] * H1D + tid];
        #pragma unroll
        for (int u = 0; u < 8; ++u)
            acc += sv[k + u] * p[u];
    }
    for (; k < cnt; ++k) acc += sv[k] * g_P1[(size_t)sc[k] * H1D + tid];
    g_H1[(size_t)row * H1D + tid] = fmaxf(acc, 0.f);
}

// ============================================================================
// K3: P2[16384,64] = H1[16384,256] @ W2[256,64]   (128x64x16 tiles, FFMA2)
// ============================================================================
__global__ void __launch_bounds__(256, 2)
k3_gemm2(const float* __restrict__ W2) {
    __shared__ float As[16 * 128];
    __shared__ float Bs[16 * 64];
    int row_base = blockIdx.x * 128;
    int tid = threadIdx.x;
    int tx = tid & 15, ty = tid >> 4;

    ull acc[8][2];
    #pragma unroll
    for (int r = 0; r < 8; ++r) { acc[r][0] = 0ull; acc[r][1] = 0ull; }

    for (int kb = 0; kb < H1D; kb += 16) {
        #pragma unroll
        for (int l = 0; l < 2; ++l) {
            int idx = tid + l * 256;
            int m  = idx & 127;
            int kq = idx >> 7;
            float4 v = *(const float4*)&g_H1[(size_t)(row_base + m) * H1D + kb + kq * 4];
            As[(kq * 4 + 0) * 128 + m] = v.x;
            As[(kq * 4 + 1) * 128 + m] = v.y;
            As[(kq * 4 + 2) * 128 + m] = v.z;
            As[(kq * 4 + 3) * 128 + m] = v.w;
        }
        {
            int kk = tid >> 4;     // 0..15
            int nq = tid & 15;     // 0..15
            float4 v = __ldg((const float4*)&W2[(size_t)(kb + kk) * H2D + nq * 4]);
            *(float4*)&Bs[kk * 64 + nq * 4] = v;
        }
        __syncthreads();
        #pragma unroll
        for (int kk = 0; kk < 16; ++kk) {
            float4 a0 = *(float4*)&As[kk * 128 + ty * 8];
            float4 a1 = *(float4*)&As[kk * 128 + ty * 8 + 4];
            ull b0 = *(ull*)&Bs[kk * 64 + tx * 4];
            ull b1 = *(ull*)&Bs[kk * 64 + tx * 4 + 2];
            float av[8] = {a0.x, a0.y, a0.z, a0.w, a1.x, a1.y, a1.z, a1.w};
            #pragma unroll
            for (int r = 0; r < 8; ++r) {
                ull ad = dup2(av[r]);
                ffma2(acc[r][0], ad, b0);
                ffma2(acc[r][1], ad, b1);
            }
        }
        __syncthreads();
    }
    #pragma unroll
    for (int r = 0; r < 8; ++r) {
        int row = row_base + ty * 8 + r;
        float2 p0 = unpack2(acc[r][0]);
        float2 p1 = unpack2(acc[r][1]);
        *(float4*)&g_P2[(size_t)row * H2D + tx * 4] = make_float4(p0.x, p0.y, p1.x, p1.y);
    }
}

// ============================================================================
// K4: H2[row,c] = b2[c] + sum_k val_k * P2[col_k, c]; column max over rows.
//     Warp-per-row (2 rows/warp), lane holds cols {2l, 2l+1} as float2.
// ============================================================================
__global__ void __launch_bounds__(256)
k4_spmm2_max(const float* __restrict__ b2) {
    int tid  = threadIdx.x;
    int w    = tid >> 5;              // warp 0..7
    int lane = tid & 31;
    __shared__ float2 red[8][32];     // per-warp column maxima

    float2 bias = __ldg((const float2*)&b2[lane * 2]);
    float2 mv = make_float2(-3.402823466e38f, -3.402823466e38f);

    #pragma unroll
    for (int rr = 0; rr < 2; ++rr) {
        int row = blockIdx.x * 16 + rr * 8 + w;
        int cnt = g_cnt[row];
        const unsigned short* cp = &g_cols[row * CAP];
        const float*          vp = &g_vals[row * CAP];
        float2 acc = bias;
        int k = 0;
        for (; k + 4 <= cnt; k += 4) {
            int   c0 = __ldg(&cp[k]),     c1 = __ldg(&cp[k + 1]);
            int   c2 = __ldg(&cp[k + 2]), c3 = __ldg(&cp[k + 3]);
            float v0 = __ldg(&vp[k]),     v1 = __ldg(&vp[k + 1]);
            float v2 = __ldg(&vp[k + 2]), v3 = __ldg(&vp[k + 3]);
            float2 p0 = *(const float2*)&g_P2[(size_t)c0 * H2D + lane * 2];
            float2 p1 = *(const float2*)&g_P2[(size_t)c1 * H2D + lane * 2];
            float2 p2 = *(const float2*)&g_P2[(size_t)c2 * H2D + lane * 2];
            float2 p3 = *(const float2*)&g_P2[(size_t)c3 * H2D + lane * 2];
            acc.x += v0 * p0.x; acc.y += v0 * p0.y;
            acc.x += v1 * p1.x; acc.y += v1 * p1.y;
            acc.x += v2 * p2.x; acc.y += v2 * p2.y;
            acc.x += v3 * p3.x; acc.y += v3 * p3.y;
        }
        for (; k < cnt; ++k) {
            int   c = __ldg(&cp[k]);
            float v = __ldg(&vp[k]);
            float2 p = *(const float2*)&g_P2[(size_t)c * H2D + lane * 2];
            acc.x += v * p.x; acc.y += v * p.y;
        }
        mv.x = fmaxf(mv.x, acc.x);
        mv.y = fmaxf(mv.y, acc.y);
    }
    red[w][lane] = mv;
    __syncthreads();
    if (w == 0) {
        float2 v = red[0][lane];
        #pragma unroll
        for (int i = 1; i < 8; ++i) {
            v.x = fmaxf(v.x, red[i][lane].x);
            v.y = fmaxf(v.y, red[i][lane].y);
        }
        *(float2*)&g_pmax[blockIdx.x * H2D + lane * 2] = v;
    }
}

// ============================================================================
// K5: reduce 1024 partial maxima -> g[64]; then tiny MLP -> out[10]
// ============================================================================
__global__ void __launch_bounds__(1024)
k5_final(const float* __restrict__ W3, const float* __restrict__ b3,
         const float* __restrict__ W4, const float* __restrict__ b4,
         const float* __restrict__ W5, const float* __restrict__ b5,
         float* __restrict__ out) {
    __shared__ float red[16][64];
    __shared__ float g[64], t3[32], t4[16];
    int tid = threadIdx.x;
    int c = tid & 63, s = tid >> 6;       // 16 segments x 64 cols
    {
        float v = -3.402823466e38f;
        int b0 = s * (K4_BLOCKS / 16);
        #pragma unroll 8
        for (int b = 0; b < K4_BLOCKS / 16; ++b)
            v = fmaxf(v, g_pmax[(b0 + b) * H2D + c]);
        red[s][c] = v;
    }
    __syncthreads();
    if (tid < 64) {
        float v = red[0][tid];
        #pragma unroll
        for (int i = 1; i < 16; ++i) v = fmaxf(v, red[i][tid]);
        g[tid] = v;
    }
    __syncthreads();
    if (tid < 32) {
        float a = b3[tid];
        for (int cc = 0; cc < 64; ++cc) a += g[cc] * W3[cc * 32 + tid];
        t3[tid] = fmaxf(a, 0.f);
    }
    __syncthreads();
    if (tid < 16) {
        float a = b4[tid];
        for (int cc = 0; cc < 32; ++cc) a += t3[cc] * W4[cc * 16 + tid];
        t4[tid] = fmaxf(a, 0.f);
    }
    __syncthreads();
    if (tid < 10) {
        float a = b5[tid];
        for (int cc = 0; cc < 16; ++cc) a += t4[cc] * W5[cc * 10 + tid];
        out[tid] = a;
    }
}

// ============================================================================
extern "C" void kernel_launch(void* const* d_in, const int* in_sizes, int n_in,
                              void* d_out, int out_size) {
    const float* x   = (const float*)d_in[0];
    const float* adj = (const float*)d_in[1];
    const float* W1  = (const float*)d_in[2];
    const float* b1  = (const float*)d_in[3];
    const float* W2  = (const float*)d_in[4];
    const float* b2  = (const float*)d_in[5];
    const float* W3  = (const float*)d_in[6];
    const float* b3  = (const float*)d_in[7];
    const float* W4  = (const float*)d_in[8];
    const float* b4  = (const float*)d_in[9];
    const float* W5  = (const float*)d_in[10];
    const float* b5  = (const float*)d_in[11];
    float* out = (float*)d_out;

    k1_scan_gemm<<<K1_GRID, 256>>>(x, adj, W1);
    k2_spmm1<<<NN, 256>>>(b1);
    k3_gemm2<<<NN / 128, 256>>>(W2);
    k4_spmm2_max<<<K4_BLOCKS, 256>>>(b2);
    k5_final<<<1, 1024>>>(W3, b3, W4, b4, W5, b5, out);
}

// round 10
// speedup vs baseline: 1.5444x; 1.5444x over previous
#include <cuda_runtime.h>

#define NN     16384
#define FEAT   512
#define H1D    256
#define H2D    64
#define CAP    128
#define SCAN_BLOCKS 148
#define K1_GRID (SCAN_BLOCKS + 148)   // one scan CTA + one GEMM CTA per SM
#define K4_BLOCKS 1024                // 16 rows per block (2 per warp)

#define STAGE_F4 64                   // float4 per scan stage (1 KB)
#define DEPTH    4                    // smem ring depth per warp
#define STAGES   (NN / 4 / STAGE_F4)  // 64 stages per row

// ---------------- scratch (static device arrays: allowed) ----------------
__device__ unsigned short g_cols[(size_t)NN * CAP];   // 4 MB
__device__ float          g_vals[(size_t)NN * CAP];   // 8 MB
__device__ int            g_cnt [NN];
__device__ float          g_P1  [(size_t)NN * H1D];   // 16 MB  x@W1
__device__ float          g_H1  [(size_t)NN * H1D];   // 16 MB  relu(A p1 + b1)
__device__ float          g_P2  [(size_t)NN * H2D];   // 4 MB   H1@W2
__device__ float          g_pmax[K4_BLOCKS * H2D];    // per-block column maxima

typedef unsigned long long ull;

__device__ __forceinline__ ull dup2(float a) {
    ull r; asm("mov.b64 %0, {%1,%1};" : "=l"(r) : "f"(a)); return r;
}
__device__ __forceinline__ void ffma2(ull& d, ull a, ull b) {
    asm("fma.rn.f32x2 %0, %1, %2, %0;" : "+l"(d) : "l"(a), "l"(b));
}
__device__ __forceinline__ float2 unpack2(ull v) {
    float2 r; asm("mov.b64 {%0,%1}, %2;" : "=f"(r.x), "=f"(r.y) : "l"(v)); return r;
}
__device__ __forceinline__ void cp16(void* smem_dst, const void* gmem_src) {
    unsigned saddr = (unsigned)__cvta_generic_to_shared(smem_dst);
    asm volatile("cp.async.cg.shared.global [%0], [%1], 16;\n"
                 :: "r"(saddr), "l"(gmem_src) : "memory");
}
__device__ __forceinline__ void cp_commit() {
    asm volatile("cp.async.commit_group;\n" ::: "memory");
}
__device__ __forceinline__ void cp_wait3() {
    asm volatile("cp.async.wait_group 3;\n" ::: "memory");
}

// ============================================================================
// K1: fused  (a) adj sparsify scan — blocks [0,148): warp-per-row,
//                cp.async 4-deep smem ring (zero register pressure, ~24KB/SM
//                in flight) + deterministic ballot compaction
//            (b) P1 = x@W1 fp32 GEMM — blocks [148,296): grid-stride over
//                256 tiles of 128x128, FFMA2 inner loop
//     Both branches overlay a 32 KB static smem pool.
// ============================================================================
__global__ void __launch_bounds__(256, 2)
k1_scan_gemm(const float* __restrict__ x,
             const float* __restrict__ adj,
             const float* __restrict__ W1) {
    __shared__ __align__(16) char s_pool[32768];

    if (blockIdx.x < SCAN_BLOCKS) {
        int lane = threadIdx.x & 31;
        int w    = threadIdx.x >> 5;
        unsigned lt = (1u << lane) - 1u;
        float4* wbuf = ((float4*)s_pool) + w * (DEPTH * STAGE_F4);   // 4 KB/warp

        for (int row = blockIdx.x * 8 + w; row < NN; row += SCAN_BLOCKS * 8) {
            const float4* r4 = (const float4*)(adj + (size_t)row * NN);
            int base = row * CAP;
            int cnt  = 0;

            // prologue: issue stages 0..2
            #pragma unroll
            for (int p = 0; p < DEPTH - 1; ++p) {
                const float4* src = r4 + p * STAGE_F4;
                #pragma unroll
                for (int u = 0; u < STAGE_F4 / 32; ++u)
                    cp16(&wbuf[p * STAGE_F4 + u * 32 + lane], &src[u * 32 + lane]);
                cp_commit();
            }

            for (int s = 0; s < STAGES; ++s) {
                int nx = s + (DEPTH - 1);
                if (nx < STAGES) {                       // issue stage s+3
                    int slot = nx & (DEPTH - 1);
                    const float4* src = r4 + nx * STAGE_F4;
                    #pragma unroll
                    for (int u = 0; u < STAGE_F4 / 32; ++u)
                        cp16(&wbuf[slot * STAGE_F4 + u * 32 + lane], &src[u * 32 + lane]);
                }
                cp_commit();                             // empty group at tail keeps count uniform
                cp_wait3();                              // stage s now resident

                int slot = s & (DEPTH - 1);
                #pragma unroll
                for (int u = 0; u < STAGE_F4 / 32; ++u) {
                    float4 vv = wbuf[slot * STAGE_F4 + u * 32 + lane];
                    int colbase = 4 * (s * STAGE_F4 + u * 32 + lane);
                    bool any = (vv.x != 0.f) || (vv.y != 0.f) || (vv.z != 0.f) || (vv.w != 0.f);
                    unsigned m4 = __ballot_sync(0xffffffffu, any);
                    if (m4 == 0u) continue;              // most chunks all-zero
                    float arr[4] = {vv.x, vv.y, vv.z, vv.w};
                    #pragma unroll
                    for (int c2 = 0; c2 < 4; ++c2) {
                        float val = arr[c2];
                        unsigned m = __ballot_sync(0xffffffffu, val != 0.f);
                        if (val != 0.f) {
                            int off = cnt + __popc(m & lt);
                            if (off < CAP) {
                                g_cols[base + off] = (unsigned short)(colbase + c2);
                                g_vals[base + off] = val;
                            }
                        }
                        cnt += __popc(m);
                    }
                }
            }
            if (lane == 0) g_cnt[row] = cnt < CAP ? cnt : CAP;
        }
    } else {
        // ---- GEMM: P1[16384,256] = x[16384,512] @ W1[512,256] ----
        float* As = (float*)s_pool;              // [k][m]  8 KB
        float* Bs = (float*)(s_pool + 8192);     // [k][n]  8 KB
        int tid = threadIdx.x;
        int tx = tid & 15, ty = tid >> 4;

        for (int t = blockIdx.x - SCAN_BLOCKS; t < 256; t += 148) {
            int row_base = (t >> 1) * 128;
            int col_base = (t & 1) * 128;

            ull acc[8][4];
            #pragma unroll
            for (int r = 0; r < 8; ++r)
                #pragma unroll
                for (int c = 0; c < 4; ++c) acc[r][c] = 0ull;

            for (int kb = 0; kb < FEAT; kb += 16) {
                #pragma unroll
                for (int l = 0; l < 2; ++l) {              // A: 512 float4
                    int idx = tid + l * 256;
                    int m  = idx & 127;
                    int kq = idx >> 7;                      // 0..3
                    float4 v = __ldg((const float4*)&x[(size_t)(row_base + m) * FEAT + kb + kq * 4]);
                    As[(kq * 4 + 0) * 128 + m] = v.x;
                    As[(kq * 4 + 1) * 128 + m] = v.y;
                    As[(kq * 4 + 2) * 128 + m] = v.z;
                    As[(kq * 4 + 3) * 128 + m] = v.w;
                }
                #pragma unroll
                for (int l = 0; l < 2; ++l) {              // B: 512 float4
                    int idx = tid + l * 256;
                    int kk = idx >> 5;                      // 0..15
                    int nq = idx & 31;
                    float4 v = __ldg((const float4*)&W1[(size_t)(kb + kk) * H1D + col_base + nq * 4]);
                    *(float4*)&Bs[kk * 128 + nq * 4] = v;
                }
                __syncthreads();
                #pragma unroll
                for (int kk = 0; kk < 16; ++kk) {
                    float4 a0 = *(float4*)&As[kk * 128 + ty * 8];
                    float4 a1 = *(float4*)&As[kk * 128 + ty * 8 + 4];
                    ull b0 = *(ull*)&Bs[kk * 128 + tx * 8];
                    ull b1 = *(ull*)&Bs[kk * 128 + tx * 8 + 2];
                    ull b2 = *(ull*)&Bs[kk * 128 + tx * 8 + 4];
                    ull b3 = *(ull*)&Bs[kk * 128 + tx * 8 + 6];
                    float av[8] = {a0.x, a0.y, a0.z, a0.w, a1.x, a1.y, a1.z, a1.w};
                    #pragma unroll
                    for (int r = 0; r < 8; ++r) {
                        ull ad = dup2(av[r]);
                        ffma2(acc[r][0], ad, b0);
                        ffma2(acc[r][1], ad, b1);
                        ffma2(acc[r][2], ad, b2);
                        ffma2(acc[r][3], ad, b3);
                    }
                }
                __syncthreads();
            }
            #pragma unroll
            for (int r = 0; r < 8; ++r) {
                int row = row_base + ty * 8 + r;
                float2 p0 = unpack2(acc[r][0]);
                float2 p1 = unpack2(acc[r][1]);
                float2 p2 = unpack2(acc[r][2]);
                float2 p3 = unpack2(acc[r][3]);
                *(float4*)&g_P1[(size_t)row * H1D + col_base + tx * 8]     = make_float4(p0.x, p0.y, p1.x, p1.y);
                *(float4*)&g_P1[(size_t)row * H1D + col_base + tx * 8 + 4] = make_float4(p2.x, p2.y, p3.x, p3.y);
            }
        }
    }
}

// ============================================================================
// K2: H1[row, c] = relu(b1[c] + sum_k val_k * P1[col_k, c])   (block per row)
// ============================================================================
__global__ void __launch_bounds__(256)
k2_spmm1(const float* __restrict__ b1) {
    int row = blockIdx.x;
    int tid = threadIdx.x;
    __shared__ int   sc[CAP];
    __shared__ float sv[CAP];
    int cnt = g_cnt[row];
    if (tid < cnt) {
        sc[tid] = g_cols[row * CAP + tid];
        sv[tid] = g_vals[row * CAP + tid];
    }
    __syncthreads();
    float acc = __ldg(&b1[tid]);
    int k = 0;
    for (; k + 8 <= cnt; k += 8) {                 // 8 gathers in flight
        float p[8];
        #pragma unroll
        for (int u = 0; u < 8; ++u)
            p[u] = g_P1[(size_t)sc[k + u] * H1D + tid];
        #pragma unroll
        for (int u = 0; u < 8; ++u)
            acc += sv[k + u] * p[u];
    }
    for (; k < cnt; ++k) acc += sv[k] * g_P1[(size_t)sc[k] * H1D + tid];
    g_H1[(size_t)row * H1D + tid] = fmaxf(acc, 0.f);
}

// ============================================================================
// K3: P2[16384,64] = H1[16384,256] @ W2[256,64]   (128x64x16 tiles, FFMA2)
// ============================================================================
__global__ void __launch_bounds__(256, 2)
k3_gemm2(const float* __restrict__ W2) {
    __shared__ float As[16 * 128];
    __shared__ float Bs[16 * 64];
    int row_base = blockIdx.x * 128;
    int tid = threadIdx.x;
    int tx = tid & 15, ty = tid >> 4;

    ull acc[8][2];
    #pragma unroll
    for (int r = 0; r < 8; ++r) { acc[r][0] = 0ull; acc[r][1] = 0ull; }

    for (int kb = 0; kb < H1D; kb += 16) {
        #pragma unroll
        for (int l = 0; l < 2; ++l) {
            int idx = tid + l * 256;
            int m  = idx & 127;
            int kq = idx >> 7;
            float4 v = *(const float4*)&g_H1[(size_t)(row_base + m) * H1D + kb + kq * 4];
            As[(kq * 4 + 0) * 128 + m] = v.x;
            As[(kq * 4 + 1) * 128 + m] = v.y;
            As[(kq * 4 + 2) * 128 + m] = v.z;
            As[(kq * 4 + 3) * 128 + m] = v.w;
        }
        {
            int kk = tid >> 4;     // 0..15
            int nq = tid & 15;     // 0..15
            float4 v = __ldg((const float4*)&W2[(size_t)(kb + kk) * H2D + nq * 4]);
            *(float4*)&Bs[kk * 64 + nq * 4] = v;
        }
        __syncthreads();
        #pragma unroll
        for (int kk = 0; kk < 16; ++kk) {
            float4 a0 = *(float4*)&As[kk * 128 + ty * 8];
            float4 a1 = *(float4*)&As[kk * 128 + ty * 8 + 4];
            ull b0 = *(ull*)&Bs[kk * 64 + tx * 4];
            ull b1 = *(ull*)&Bs[kk * 64 + tx * 4 + 2];
            float av[8] = {a0.x, a0.y, a0.z, a0.w, a1.x, a1.y, a1.z, a1.w};
            #pragma unroll
            for (int r = 0; r < 8; ++r) {
                ull ad = dup2(av[r]);
                ffma2(acc[r][0], ad, b0);
                ffma2(acc[r][1], ad, b1);
            }
        }
        __syncthreads();
    }
    #pragma unroll
    for (int r = 0; r < 8; ++r) {
        int row = row_base + ty * 8 + r;
        float2 p0 = unpack2(acc[r][0]);
        float2 p1 = unpack2(acc[r][1]);
        *(float4*)&g_P2[(size_t)row * H2D + tx * 4] = make_float4(p0.x, p0.y, p1.x, p1.y);
    }
}

// ============================================================================
// K4: H2[row,c] = b2[c] + sum_k val_k * P2[col_k, c]; column max over rows.
//     Warp-per-row (2 rows/warp), lane holds cols {2l, 2l+1} as float2.
// ============================================================================
__global__ void __launch_bounds__(256)
k4_spmm2_max(const float* __restrict__ b2) {
    int tid  = threadIdx.x;
    int w    = tid >> 5;              // warp 0..7
    int lane = tid & 31;
    __shared__ float2 red[8][32];     // per-warp column maxima

    float2 bias = __ldg((const float2*)&b2[lane * 2]);
    float2 mv = make_float2(-3.402823466e38f, -3.402823466e38f);

    #pragma unroll
    for (int rr = 0; rr < 2; ++rr) {
        int row = blockIdx.x * 16 + rr * 8 + w;
        int cnt = g_cnt[row];
        const unsigned short* cp = &g_cols[row * CAP];
        const float*          vp = &g_vals[row * CAP];
        float2 acc = bias;
        int k = 0;
        for (; k + 4 <= cnt; k += 4) {
            int   c0 = __ldg(&cp[k]),     c1 = __ldg(&cp[k + 1]);
            int   c2 = __ldg(&cp[k + 2]), c3 = __ldg(&cp[k + 3]);
            float v0 = __ldg(&vp[k]),     v1 = __ldg(&vp[k + 1]);
            float v2 = __ldg(&vp[k + 2]), v3 = __ldg(&vp[k + 3]);
            float2 p0 = *(const float2*)&g_P2[(size_t)c0 * H2D + lane * 2];
            float2 p1 = *(const float2*)&g_P2[(size_t)c1 * H2D + lane * 2];
            float2 p2 = *(const float2*)&g_P2[(size_t)c2 * H2D + lane * 2];
            float2 p3 = *(const float2*)&g_P2[(size_t)c3 * H2D + lane * 2];
            acc.x += v0 * p0.x; acc.y += v0 * p0.y;
            acc.x += v1 * p1.x; acc.y += v1 * p1.y;
            acc.x += v2 * p2.x; acc.y += v2 * p2.y;
            acc.x += v3 * p3.x; acc.y += v3 * p3.y;
        }
        for (; k < cnt; ++k) {
            int   c = __ldg(&cp[k]);
            float v = __ldg(&vp[k]);
            float2 p = *(const float2*)&g_P2[(size_t)c * H2D + lane * 2];
            acc.x += v * p.x; acc.y += v * p.y;
        }
        mv.x = fmaxf(mv.x, acc.x);
        mv.y = fmaxf(mv.y, acc.y);
    }
    red[w][lane] = mv;
    __syncthreads();
    if (w == 0) {
        float2 v = red[0][lane];
        #pragma unroll
        for (int i = 1; i < 8; ++i) {
            v.x = fmaxf(v.x, red[i][lane].x);
            v.y = fmaxf(v.y, red[i][lane].y);
        }
        *(float2*)&g_pmax[blockIdx.x * H2D + lane * 2] = v;
    }
}

// ============================================================================
// K5: reduce 1024 partial maxima -> g[64]; then tiny MLP -> out[10]
// ============================================================================
__global__ void __launch_bounds__(1024)
k5_final(const float* __restrict__ W3, const float* __restrict__ b3,
         const float* __restrict__ W4, const float* __restrict__ b4,
         const float* __restrict__ W5, const float* __restrict__ b5,
         float* __restrict__ out) {
    __shared__ float red[16][64];
    __shared__ float g[64], t3[32], t4[16];
    int tid = threadIdx.x;
    int c = tid & 63, s = tid >> 6;       // 16 segments x 64 cols
    {
        float v = -3.402823466e38f;
        int b0 = s * (K4_BLOCKS / 16);
        #pragma unroll 8
        for (int b = 0; b < K4_BLOCKS / 16; ++b)
            v = fmaxf(v, g_pmax[(b0 + b) * H2D + c]);
        red[s][c] = v;
    }
    __syncthreads();
    if (tid < 64) {
        float v = red[0][tid];
        #pragma unroll
        for (int i = 1; i < 16; ++i) v = fmaxf(v, red[i][tid]);
        g[tid] = v;
    }
    __syncthreads();
    if (tid < 32) {
        float a = b3[tid];
        for (int cc = 0; cc < 64; ++cc) a += g[cc] * W3[cc * 32 + tid];
        t3[tid] = fmaxf(a, 0.f);
    }
    __syncthreads();
    if (tid < 16) {
        float a = b4[tid];
        for (int cc = 0; cc < 32; ++cc) a += t3[cc] * W4[cc * 16 + tid];
        t4[tid] = fmaxf(a, 0.f);
    }
    __syncthreads();
    if (tid < 10) {
        float a = b5[tid];
        for (int cc = 0; cc < 16; ++cc) a += t4[cc] * W5[cc * 10 + tid];
        out[tid] = a;
    }
}

// ============================================================================
extern "C" void kernel_launch(void* const* d_in, const int* in_sizes, int n_in,
                              void* d_out, int out_size) {
    const float* x   = (const float*)d_in[0];
    const float* adj = (const float*)d_in[1];
    const float* W1  = (const float*)d_in[2];
    const float* b1  = (const float*)d_in[3];
    const float* W2  = (const float*)d_in[4];
    const float* b2  = (const float*)d_in[5];
    const float* W3  = (const float*)d_in[6];
    const float* b3  = (const float*)d_in[7];
    const float* W4  = (const float*)d_in[8];
    const float* b4  = (const float*)d_in[9];
    const float* W5  = (const float*)d_in[10];
    const float* b5  = (const float*)d_in[11];
    float* out = (float*)d_out;

    k1_scan_gemm<<<K1_GRID, 256>>>(x, adj, W1);
    k2_spmm1<<<NN, 256>>>(b1);
    k3_gemm2<<<NN / 128, 256>>>(W2);
    k4_spmm2_max<<<K4_BLOCKS, 256>>>(b2);
    k5_final<<<1, 1024>>>(W3, b3, W4, b4, W5, b5, out);
}